// round 13
// baseline (speedup 1.0000x reference)
#include <cuda_runtime.h>
#include <cuda_fp16.h>
#include <math.h>
#include <stdint.h>

// Problem constants (fixed by dataset)
#define B_SAMPLES 4096
#define H_DIM 256
#define C_CH 8
#define K_EXP 3
#define L_DIM 8192   // N*D = 64*128

#define TILE_MAX 35
#define NSPLIT 2
#define KSEG (L_DIM / NSPLIT)   // 4096
#define KT 64
#define NIT (KSEG / KT)         // 64
#define AST 72                  // smem row stride in fp16 elements (64 + 8 pad)

// ---------------- scratch (device globals; no allocation allowed) ----------------
__device__ int   g_off[K_EXP + 1];
__device__ int   g_idx[B_SAMPLES];
__device__ float g_w2h[K_EXP * H_DIM];
__device__ float g_c2h[K_EXP];
__device__ float g_logits[B_SAMPLES];
__device__ int   g_tile_g[TILE_MAX];
__device__ int   g_tile_r0[TILE_MAX];
__device__ int   g_ntiles;
// W1 transposed, fp16: [K_EXP][H][L]
__device__ __half g_w1h[K_EXP * H_DIM * L_DIM];
// split-K partials: [split][tile][nhalf][row(128)][col(128)]
__device__ float g_part[NSPLIT * TILE_MAX * 2 * 128 * 128];

// ---------------- PTX helpers (arch-agnostic: ldmatrix + mma.sync + cp.async) ----
__device__ __forceinline__ uint32_t smem_u32(const void* p) {
    uint32_t a;
    asm("{ .reg .u64 t; cvta.to.shared.u64 t, %1; cvt.u32.u64 %0, t; }" : "=r"(a) : "l"(p));
    return a;
}
__device__ __forceinline__ void ldsm_x4(uint32_t* r, uint32_t addr) {
    asm volatile("ldmatrix.sync.aligned.m8n8.x4.shared.b16 {%0,%1,%2,%3}, [%4];"
        : "=r"(r[0]), "=r"(r[1]), "=r"(r[2]), "=r"(r[3]) : "r"(addr));
}
__device__ __forceinline__ void mma_f16(float* d, const uint32_t* a, const uint32_t* b) {
    asm volatile("mma.sync.aligned.m16n8k16.row.col.f32.f16.f16.f32 "
        "{%0,%1,%2,%3}, {%4,%5,%6,%7}, {%8,%9}, {%0,%1,%2,%3};"
        : "+f"(d[0]), "+f"(d[1]), "+f"(d[2]), "+f"(d[3])
        : "r"(a[0]), "r"(a[1]), "r"(a[2]), "r"(a[3]), "r"(b[0]), "r"(b[1]));
}
__device__ __forceinline__ void cp16(uint32_t dst, const void* src) {
    asm volatile("cp.async.cg.shared.global [%0], [%1], 16;" :: "r"(dst), "l"(src));
}
#define CP_COMMIT() asm volatile("cp.async.commit_group;" ::: "memory")
#define CP_WAIT0()  asm volatile("cp.async.wait_group 0;" ::: "memory")
#define CP_WAIT1()  asm volatile("cp.async.wait_group 1;" ::: "memory")

// ---------------- 1) fused setup: thresholds + grouping + scatter + tiles --------
// One block, 1024 threads. Exact fp32 op sequence of the reference quantile math.
__global__ void __launch_bounds__(1024) k_setup(const float* __restrict__ q,
                                                const int* __restrict__ ch, int B) {
    __shared__ float sq[B_SAMPLES];           // 16 KB
    __shared__ unsigned char sch[B_SAMPLES];  // 4 KB
    __shared__ float vals[B_SAMPLES];         // 16 KB (channel-compacted q)
    __shared__ int   ccnt[C_CH], cfill[C_CH], coff[C_CH + 1];
    __shared__ int   ciu[C_CH], cil[C_CH];
    __shared__ float uq[C_CH], lq[C_CH];
    __shared__ int   ecnt[K_EXP], efill[K_EXP], eoff[K_EXP + 1];
    int tid = threadIdx.x;
    if (tid < C_CH) { ccnt[tid] = 0; cfill[tid] = 0; }
    if (tid < K_EXP) { ecnt[tid] = 0; efill[tid] = 0; }
    __syncthreads();
    #pragma unroll
    for (int j = 0; j < 4; j++) {
        int b = tid + j * 1024;
        float v = q[b]; int c = ch[b];
        sq[b] = v; sch[b] = (unsigned char)c;
        atomicAdd(&ccnt[c], 1);
    }
    __syncthreads();
    if (tid == 0) {
        coff[0] = 0;
        for (int c = 0; c < C_CH; c++) coff[c + 1] = coff[c] + ccnt[c];
    }
    __syncthreads();
    #pragma unroll
    for (int j = 0; j < 4; j++) {
        int b = tid + j * 1024;
        int c = sch[b];
        int p = atomicAdd(&cfill[c], 1);
        vals[coff[c] + p] = sq[b];
    }
    if (tid < C_CH) {
        float nf = (float)ccnt[tid];
        float au = ceilf((nf + 1.0f) * 0.9f) / nf;
        float pu = (au > 1.0f) ? 0.9f : au;
        float al = floorf((nf + 1.0f) * 0.1f) / nf;
        float pl = (al < 0.0f) ? 0.1f : al;
        ciu[tid] = (int)floorf(pu * (nf - 1.0f));
        cil[tid] = (int)floorf(pl * (nf - 1.0f));
    }
    __syncthreads();
    // rank-count selection per channel segment (duplicates share value)
    for (int e = tid; e < B; e += 1024) {
        int c = 0;
        while (e >= coff[c + 1]) c++;
        int base = coff[c], n = ccnt[c];
        float v = vals[e];
        int lt = 0, eq = 0;
        for (int j = 0; j < n; j++) { float w = vals[base + j]; lt += (w < v); eq += (w == v); }
        if (lt <= ciu[c] && ciu[c] < lt + eq) uq[c] = v;
        if (lt <= cil[c] && cil[c] < lt + eq) lq[c] = v;
    }
    __syncthreads();
    // grouping (lower wins on overlap) + expert counts
    int myg[4];
    #pragma unroll
    for (int j = 0; j < 4; j++) {
        int b = tid + j * 1024;
        int c = sch[b];
        float v = sq[b];
        int g = (v <= lq[c]) ? 2 : ((v >= uq[c]) ? 0 : 1);
        myg[j] = g;
        atomicAdd(&ecnt[g], 1);
    }
    __syncthreads();
    if (tid == 0) {
        eoff[0] = 0;
        for (int k = 0; k < K_EXP; k++) eoff[k + 1] = eoff[k] + ecnt[k];
        for (int k = 0; k <= K_EXP; k++) g_off[k] = eoff[k];
        int nt = 0;
        for (int k = 0; k < K_EXP; k++)
            for (int t0 = 0; t0 < ecnt[k]; t0 += 128) {
                g_tile_g[nt] = k; g_tile_r0[nt] = t0; nt++;
            }
        g_ntiles = nt;
    }
    __syncthreads();
    #pragma unroll
    for (int j = 0; j < 4; j++) {
        int b = tid + j * 1024;
        int g = myg[j];
        int p = atomicAdd(&efill[g], 1);
        g_idx[eoff[g] + p] = b;
    }
}

// ---------------- 2) merged prep: convW1 (6144 blocks) + w2h (96) + c2h (3) ------
#define PREP_CONV 6144   // (L_DIM/32) * (H_DIM/32) * K_EXP = 256*8*3
#define PREP_W2H  96     // 96 * 8 warps = 768 = K_EXP*H_DIM
#define PREP_BLKS (PREP_CONV + PREP_W2H + K_EXP)

__global__ void __launch_bounds__(256) k_prep(const float* __restrict__ W1,
                                              const float* __restrict__ W2,
                                              const float* __restrict__ Wh,
                                              const float* __restrict__ b2,
                                              const float* __restrict__ bh) {
    int blk = blockIdx.x;
    int tid = threadIdx.x;
    if (blk < PREP_CONV) {
        // --- W1 transpose to fp16: tile (l0, h0, k) ---
        __shared__ float s[32][33];
        int k  = blk / (256 * 8);
        int rem = blk % (256 * 8);
        int l0 = (rem % 256) * 32;
        int h0 = (rem / 256) * 32;
        int tx = tid & 31, ty = tid >> 5;   // (32, 8)
        #pragma unroll
        for (int i = 0; i < 4; i++) {
            int l = l0 + ty + i * 8;
            s[ty + i * 8][tx] = W1[((size_t)k * L_DIM + l) * H_DIM + h0 + tx];
        }
        __syncthreads();
        #pragma unroll
        for (int i = 0; i < 4; i++) {
            int h = h0 + ty + i * 8;
            int l = l0 + tx;
            g_w1h[((size_t)k * H_DIM + h) * L_DIM + l] = __float2half_rn(s[tx][ty + i * 8]);
        }
    } else if (blk < PREP_CONV + PREP_W2H) {
        // --- w2h[k][h] = sum_l W2[k][h][l] * Wh[k][l], one warp per (k,h) ---
        int wrp  = (blk - PREP_CONV) * 8 + (tid >> 5);
        int lane = tid & 31;
        int k = wrp / H_DIM, h = wrp % H_DIM;
        const float* w2row = W2 + ((size_t)k * H_DIM + h) * L_DIM;
        const float* whrow = Wh + (size_t)k * L_DIM;
        float s = 0.f;
        #pragma unroll 8
        for (int l = lane; l < L_DIM; l += 32) s += w2row[l] * whrow[l];
        #pragma unroll
        for (int o = 16; o; o >>= 1) s += __shfl_xor_sync(0xffffffffu, s, o);
        if (lane == 0) g_w2h[k * H_DIM + h] = s;
    } else {
        // --- c2h[k] = b2[k] . Wh[k] + bh[k] ---
        __shared__ float red[256];
        int k = blk - PREP_CONV - PREP_W2H;
        const float* bp = b2 + (size_t)k * L_DIM;
        const float* wp = Wh + (size_t)k * L_DIM;
        float s = 0.f;
        #pragma unroll 8
        for (int l = tid; l < L_DIM; l += 256) s += bp[l] * wp[l];
        red[tid] = s; __syncthreads();
        for (int st = 128; st; st >>= 1) { if (tid < st) red[tid] += red[tid + st]; __syncthreads(); }
        if (tid == 0) g_c2h[k] = red[0] + bh[k];
    }
}

// ---------------- 3) fp16 mma.sync GEMM: 128x128, occ-1, 3-deep B pipeline --------
// (R11 config verbatim — converged local optimum)
// SMEM: [0,512) row ids; A double buffer @SM_A; B triple buffer @SM_B
#define TSZ   (128 * AST * 2)     // 18432
#define SM_A  1024
#define SM_B  (SM_A + 2 * TSZ)
#define SMEM_GEMM (SM_B + 3 * TSZ)   // 93184

__global__ void __launch_bounds__(256, 1) k_gemm(const float* __restrict__ zf) {
    int tile = blockIdx.x;
    if (tile >= g_ntiles) return;
    int nh = blockIdx.y, split = blockIdx.z;
    extern __shared__ char smem[];
    uint32_t sb = smem_u32(smem);
    int tid = threadIdx.x, wid = tid >> 5, lane = tid & 31;
    int wm = wid >> 2, wn = wid & 3;   // 2 x 4 warp grid; warp tile 64m x 32n

    int g = g_tile_g[tile], r0 = g_tile_r0[tile];
    int off = g_off[g], cnt = g_off[g + 1] - off;
    if (tid < 128) ((int*)smem)[tid] = g_idx[off + min(r0 + tid, cnt - 1)];
    __syncthreads();

    // A gmem pointers (8 float4 per thread per K-tile)
    const float* arow[8];
    uint32_t a_st[8];
    #pragma unroll
    for (int i = 0; i < 8; i++) {
        int chunk = tid + 256 * i;
        int row = chunk >> 4, c4 = chunk & 15;
        arow[i] = zf + (size_t)(((const int*)smem)[row]) * L_DIM + split * KSEG + c4 * 4;
        a_st[i] = (uint32_t)(row * AST + c4 * 4) * 2;
    }
    // B gmem pointers (4 x 16B per thread per K-tile)
    const __half* bhp[4];
    uint32_t b_st[4];
    #pragma unroll
    for (int i = 0; i < 4; i++) {
        int chunk = tid + 256 * i;
        int r = chunk >> 3, c = chunk & 7;
        bhp[i] = g_w1h + ((size_t)g * H_DIM + nh * 128 + r) * L_DIM + split * KSEG + c * 8;
        b_st[i] = (uint32_t)(r * AST + c * 8) * 2;
    }
    // ldmatrix per-thread base offsets
    uint32_t a_ld = (uint32_t)((wm * 64 + (lane & 15)) * AST + (lane >> 4) * 8) * 2;
    uint32_t b_ld = (uint32_t)((wn * 32 + (lane & 7) + ((lane >> 4) << 3)) * AST
                               + ((lane >> 3) & 1) * 8) * 2;

    float acc[4][4][4];
    #pragma unroll
    for (int mi = 0; mi < 4; mi++)
        #pragma unroll
        for (int ni = 0; ni < 4; ni++)
            #pragma unroll
            for (int r = 0; r < 4; r++) acc[mi][ni][r] = 0.f;

    float4 areg[8];
    // prologue: commit B(0), B(1) as separate groups; A(0) -> STS buf0; A(1) -> regs
    #pragma unroll
    for (int i = 0; i < 4; i++) cp16(sb + SM_B + b_st[i], bhp[i]);
    CP_COMMIT();
    #pragma unroll
    for (int i = 0; i < 4; i++) cp16(sb + SM_B + TSZ + b_st[i], bhp[i] + KT);
    CP_COMMIT();
    #pragma unroll
    for (int i = 0; i < 8; i++) areg[i] = *(const float4*)(arow[i]);
    #pragma unroll
    for (int i = 0; i < 8; i++) {
        float4 v = areg[i];
        __half2 h01 = __floats2half2_rn(v.x, v.y);
        __half2 h23 = __floats2half2_rn(v.z, v.w);
        *(uint2*)(smem + SM_A + a_st[i]) = make_uint2(*(uint32_t*)&h01, *(uint32_t*)&h23);
    }
    #pragma unroll
    for (int i = 0; i < 8; i++) areg[i] = *(const float4*)(arow[i] + KT);

    for (int t = 0; t < NIT; t++) {
        uint32_t a_bo = (t & 1) ? TSZ : 0;
        uint32_t a_bn = (t & 1) ? 0 : TSZ;
        uint32_t b_bo = (uint32_t)(t % 3) * TSZ;
        bool more = (t + 1 < NIT);

        // wait B(t): with B(t+1) still in flight, wait_group 1; drain fully at the end
        if (more) { CP_WAIT1(); } else { CP_WAIT0(); }
        __syncthreads();   // A(t) STS + B(t) visible; tile t-1 reads complete

        // commit B(t+2) into buf (t+2)%3 — gets TWO MMA sections to land
        if (t + 2 < NIT) {
            int kn = (t + 2) * KT;
            uint32_t b_bn = (uint32_t)((t + 2) % 3) * TSZ;
            #pragma unroll
            for (int i = 0; i < 4; i++) cp16(sb + SM_B + b_bn + b_st[i], bhp[i] + kn);
            CP_COMMIT();
        }

        // MMA ks = 0,1 on bufs (a_bo, b_bo)
        #pragma unroll
        for (int ks = 0; ks < 2; ks++) {
            uint32_t ah[4][4], bf[8];
            #pragma unroll
            for (int mi = 0; mi < 4; mi++)
                ldsm_x4(ah[mi], sb + SM_A + a_bo + a_ld + (uint32_t)(mi * 16 * AST) * 2 + ks * 32);
            ldsm_x4(bf + 0, sb + SM_B + b_bo + b_ld + ks * 32);
            ldsm_x4(bf + 4, sb + SM_B + b_bo + b_ld + (uint32_t)(16 * AST) * 2 + ks * 32);
            #pragma unroll
            for (int mi = 0; mi < 4; mi++)
                #pragma unroll
                for (int ni = 0; ni < 4; ni++)
                    mma_f16(acc[mi][ni], ah[mi], bf + ni * 2);
        }

        // A(t+1) convert + STS into a_bn (overlapped with MMAs); then LDG A(t+2)
        if (more) {
            #pragma unroll
            for (int i = 0; i < 8; i++) {
                float4 v = areg[i];
                __half2 h01 = __floats2half2_rn(v.x, v.y);
                __half2 h23 = __floats2half2_rn(v.z, v.w);
                *(uint2*)(smem + SM_A + a_bn + a_st[i]) =
                    make_uint2(*(uint32_t*)&h01, *(uint32_t*)&h23);
            }
            if (t + 2 < NIT) {
                int k2 = (t + 2) * KT;
                #pragma unroll
                for (int i = 0; i < 8; i++) areg[i] = *(const float4*)(arow[i] + k2);
            }
        }

        // MMA ks = 2,3 on bufs (a_bo, b_bo)
        #pragma unroll
        for (int ks = 2; ks < 4; ks++) {
            uint32_t ah[4][4], bf[8];
            #pragma unroll
            for (int mi = 0; mi < 4; mi++)
                ldsm_x4(ah[mi], sb + SM_A + a_bo + a_ld + (uint32_t)(mi * 16 * AST) * 2 + ks * 32);
            ldsm_x4(bf + 0, sb + SM_B + b_bo + b_ld + ks * 32);
            ldsm_x4(bf + 4, sb + SM_B + b_bo + b_ld + (uint32_t)(16 * AST) * 2 + ks * 32);
            #pragma unroll
            for (int mi = 0; mi < 4; mi++)
                #pragma unroll
                for (int ni = 0; ni < 4; ni++)
                    mma_f16(acc[mi][ni], ah[mi], bf + ni * 2);
        }
        // no trailing sync: next iteration's sync (after CP_WAIT) provides the barrier
    }

    // store fp32 partials
    float* pb = g_part + ((size_t)(split * TILE_MAX + tile) * 2 + nh) * (128 * 128);
    #pragma unroll
    for (int mi = 0; mi < 4; mi++)
        #pragma unroll
        for (int ni = 0; ni < 4; ni++) {
            int row = wm * 64 + mi * 16 + (lane >> 2);
            int col = wn * 32 + ni * 8 + (lane & 3) * 2;
            *(float2*)(pb + (size_t)row * 128 + col)       = make_float2(acc[mi][ni][0], acc[mi][ni][1]);
            *(float2*)(pb + (size_t)(row + 8) * 128 + col) = make_float2(acc[mi][ni][2], acc[mi][ni][3]);
        }
}

// ---------------- 4) reduce split-K + bias + exact gelu + head dot ----------------
// grid (TILE_MAX, 4): each block handles 32 rows of one tile (140 CTAs total)
__global__ void __launch_bounds__(256) k_epi(const float* __restrict__ b1) {
    int tile = blockIdx.x;
    if (tile >= g_ntiles) return;
    int g = g_tile_g[tile], r0 = g_tile_r0[tile];
    int off = g_off[g], cnt = g_off[g + 1] - off;
    int wid = threadIdx.x >> 5, lane = threadIdx.x & 31;
    int rbase = blockIdx.y * 32;
    float c2 = g_c2h[g];
    for (int rr = rbase + wid; rr < rbase + 32; rr += 8) {
        int r = r0 + rr;
        if (r >= cnt) continue;
        float acc = 0.f;
        #pragma unroll
        for (int j = 0; j < 8; j++) {
            int c = lane + 32 * j;
            int nh2 = c >> 7, cc = c & 127;
            float x = 0.f;
            #pragma unroll
            for (int s = 0; s < NSPLIT; s++)
                x += g_part[(((size_t)(s * TILE_MAX + tile) * 2 + nh2) * 128 + rr) * 128 + cc];
            x += b1[g * H_DIM + c];
            float ge = 0.5f * x * (1.0f + erff(x * 0.7071067811865475f));
            acc += ge * g_w2h[g * H_DIM + c];
        }
        #pragma unroll
        for (int o = 16; o; o >>= 1) acc += __shfl_xor_sync(0xffffffffu, acc, o);
        if (lane == 0) g_logits[g_idx[off + r]] = acc + c2;
    }
}

// ---------------- 5) per-channel softmax, scaled by q ----------------
__global__ void k_softmax(const float* __restrict__ q, const int* __restrict__ ch,
                          float* __restrict__ out, int B) {
    int c = blockIdx.x;
    __shared__ float red[256];
    int tid = threadIdx.x;
    float m = -INFINITY;
    for (int b = tid; b < B; b += 256) if (ch[b] == c) m = fmaxf(m, g_logits[b]);
    red[tid] = m; __syncthreads();
    for (int s = 128; s; s >>= 1) { if (tid < s) red[tid] = fmaxf(red[tid], red[tid + s]); __syncthreads(); }
    m = red[0]; __syncthreads();
    float sum = 0.f;
    for (int b = tid; b < B; b += 256) if (ch[b] == c) sum += expf(g_logits[b] - m);
    red[tid] = sum; __syncthreads();
    for (int s = 128; s; s >>= 1) { if (tid < s) red[tid] += red[tid + s]; __syncthreads(); }
    sum = red[0];
    for (int b = tid; b < B; b += 256)
        if (ch[b] == c) out[b] = q[b] * (expf(g_logits[b] - m) / sum);
}

// ---------------- launch ----------------
extern "C" void kernel_launch(void* const* d_in, const int* in_sizes, int n_in,
                              void* d_out, int out_size) {
    const float* z  = (const float*)d_in[0];
    const float* q  = (const float*)d_in[1];
    const int*   ch = (const int*)  d_in[2];
    const float* W1 = (const float*)d_in[3];
    const float* b1 = (const float*)d_in[4];
    const float* W2 = (const float*)d_in[5];
    const float* b2 = (const float*)d_in[6];
    const float* Wh = (const float*)d_in[7];
    const float* bh = (const float*)d_in[8];
    float* out = (float*)d_out;
    int B = in_sizes[1];

    static int smem_set = 0;
    if (!smem_set) {
        cudaFuncSetAttribute(k_gemm, cudaFuncAttributeMaxDynamicSharedMemorySize, SMEM_GEMM);
        smem_set = 1;
    }

    k_setup<<<1, 1024>>>(q, ch, B);
    k_prep<<<PREP_BLKS, 256>>>(W1, W2, Wh, b2, bh);
    k_gemm<<<dim3(TILE_MAX, 2, NSPLIT), 256, SMEM_GEMM>>>(z);
    k_epi<<<dim3(TILE_MAX, 4), 256>>>(b1);
    k_softmax<<<C_CH, 256>>>(q, ch, out, B);
}

// round 14
// speedup vs baseline: 1.6293x; 1.6293x over previous
#include <cuda_runtime.h>
#include <cuda_fp16.h>
#include <math.h>
#include <stdint.h>

// Problem constants (fixed by dataset)
#define B_SAMPLES 4096
#define H_DIM 256
#define C_CH 8
#define K_EXP 3
#define L_DIM 8192   // N*D = 64*128

#define TILE_MAX 35
#define NSPLIT 2
#define KSEG (L_DIM / NSPLIT)   // 4096
#define KT 64
#define NIT (KSEG / KT)         // 64
#define AST 72                  // smem row stride in fp16 elements (64 + 8 pad)

// ---------------- scratch (device globals; no allocation allowed) ----------------
__device__ float g_uq[C_CH], g_lq[C_CH];
__device__ int   g_off[K_EXP + 1];
__device__ int   g_idx[B_SAMPLES];
__device__ float g_w2h[K_EXP * H_DIM];
__device__ float g_c2h[K_EXP];
__device__ float g_logits[B_SAMPLES];
__device__ int   g_tile_g[TILE_MAX];
__device__ int   g_tile_r0[TILE_MAX];
__device__ int   g_ntiles;
// W1 transposed, fp16: [K_EXP][H][L]
__device__ __half g_w1h[K_EXP * H_DIM * L_DIM];
// split-K partials: [split][tile][nhalf][row(128)][col(128)]
__device__ float g_part[NSPLIT * TILE_MAX * 2 * 128 * 128];

// ---------------- PTX helpers (arch-agnostic: ldmatrix + mma.sync + cp.async) ----
__device__ __forceinline__ uint32_t smem_u32(const void* p) {
    uint32_t a;
    asm("{ .reg .u64 t; cvta.to.shared.u64 t, %1; cvt.u32.u64 %0, t; }" : "=r"(a) : "l"(p));
    return a;
}
__device__ __forceinline__ void ldsm_x4(uint32_t* r, uint32_t addr) {
    asm volatile("ldmatrix.sync.aligned.m8n8.x4.shared.b16 {%0,%1,%2,%3}, [%4];"
        : "=r"(r[0]), "=r"(r[1]), "=r"(r[2]), "=r"(r[3]) : "r"(addr));
}
__device__ __forceinline__ void mma_f16(float* d, const uint32_t* a, const uint32_t* b) {
    asm volatile("mma.sync.aligned.m16n8k16.row.col.f32.f16.f16.f32 "
        "{%0,%1,%2,%3}, {%4,%5,%6,%7}, {%8,%9}, {%0,%1,%2,%3};"
        : "+f"(d[0]), "+f"(d[1]), "+f"(d[2]), "+f"(d[3])
        : "r"(a[0]), "r"(a[1]), "r"(a[2]), "r"(a[3]), "r"(b[0]), "r"(b[1]));
}
__device__ __forceinline__ void cp16(uint32_t dst, const void* src) {
    asm volatile("cp.async.cg.shared.global [%0], [%1], 16;" :: "r"(dst), "l"(src));
}
#define CP_COMMIT() asm volatile("cp.async.commit_group;" ::: "memory")
#define CP_WAIT0()  asm volatile("cp.async.wait_group 0;" ::: "memory")
#define CP_WAIT1()  asm volatile("cp.async.wait_group 1;" ::: "memory")

// ---------------- 1) merged prep: thresh(8) + c2h(3) + w2h(96) + convW1(6144) ----
#define PREP_TH   C_CH                       // blocks 0..7: per-channel thresholds
#define PREP_C2H  (PREP_TH + K_EXP)          // 8..10
#define PREP_W2HE (PREP_C2H + 96)            // 11..106
#define PREP_CONV 6144                       // (L/32)*(H/32)*K = 256*8*3
#define PREP_BLKS (PREP_W2HE + PREP_CONV)    // 6251

__global__ void __launch_bounds__(256) k_prep(const float* __restrict__ W1,
                                              const float* __restrict__ W2,
                                              const float* __restrict__ Wh,
                                              const float* __restrict__ b2,
                                              const float* __restrict__ bh,
                                              const float* __restrict__ q,
                                              const int* __restrict__ ch) {
    __shared__ float sbuf[B_SAMPLES];   // 16 KB (thresh vals; conv reuses a corner)
    __shared__ int   sint[4];
    int blk = blockIdx.x;
    int tid = threadIdx.x;
    if (blk < PREP_TH) {
        // --- per-channel quantile thresholds (exact reference fp32 op order) ---
        int c = blk;
        if (tid == 0) sint[0] = 0;
        __syncthreads();
        for (int b = tid; b < B_SAMPLES; b += 256)
            if (ch[b] == c) { int p = atomicAdd(&sint[0], 1); sbuf[p] = q[b]; }
        __syncthreads();
        int n = sint[0];
        if (tid == 0) {
            float nf = (float)n;
            float au = ceilf((nf + 1.0f) * 0.9f) / nf;
            float pu = (au > 1.0f) ? 0.9f : au;
            float al = floorf((nf + 1.0f) * 0.1f) / nf;
            float pl = (al < 0.0f) ? 0.1f : al;
            sint[1] = (int)floorf(pu * (nf - 1.0f));
            sint[2] = (int)floorf(pl * (nf - 1.0f));
        }
        __syncthreads();
        int iu = sint[1], il = sint[2];
        for (int e = tid; e < n; e += 256) {
            float v = sbuf[e];
            int lt = 0, eq = 0;
            for (int j = 0; j < n; j++) { float w = sbuf[j]; lt += (w < v); eq += (w == v); }
            if (lt <= iu && iu < lt + eq) g_uq[c] = v;
            if (lt <= il && il < lt + eq) g_lq[c] = v;
        }
    } else if (blk < PREP_C2H) {
        // --- c2h[k] = b2[k] . Wh[k] + bh[k] ---
        int k = blk - PREP_TH;
        const float* bp = b2 + (size_t)k * L_DIM;
        const float* wp = Wh + (size_t)k * L_DIM;
        float s = 0.f;
        #pragma unroll 8
        for (int l = tid; l < L_DIM; l += 256) s += bp[l] * wp[l];
        sbuf[tid] = s; __syncthreads();
        for (int st = 128; st; st >>= 1) { if (tid < st) sbuf[tid] += sbuf[tid + st]; __syncthreads(); }
        if (tid == 0) g_c2h[k] = sbuf[0] + bh[k];
    } else if (blk < PREP_W2HE) {
        // --- w2h[k][h] = sum_l W2[k][h][l] * Wh[k][l], one warp per (k,h) ---
        int wrp  = (blk - PREP_C2H) * 8 + (tid >> 5);
        int lane = tid & 31;
        int k = wrp / H_DIM, h = wrp % H_DIM;
        const float* w2row = W2 + ((size_t)k * H_DIM + h) * L_DIM;
        const float* whrow = Wh + (size_t)k * L_DIM;
        float s = 0.f;
        #pragma unroll 8
        for (int l = lane; l < L_DIM; l += 32) s += w2row[l] * whrow[l];
        #pragma unroll
        for (int o = 16; o; o >>= 1) s += __shfl_xor_sync(0xffffffffu, s, o);
        if (lane == 0) g_w2h[k * H_DIM + h] = s;
    } else {
        // --- W1 transpose to fp16: tile (l0, h0, k); smem tile 32x33 in sbuf ---
        int cb = blk - PREP_W2HE;
        int k  = cb / (256 * 8);
        int rem = cb % (256 * 8);
        int l0 = (rem % 256) * 32;
        int h0 = (rem / 256) * 32;
        int tx = tid & 31, ty = tid >> 5;   // (32, 8)
        #pragma unroll
        for (int i = 0; i < 4; i++) {
            int l = l0 + ty + i * 8;
            sbuf[(ty + i * 8) * 33 + tx] = W1[((size_t)k * L_DIM + l) * H_DIM + h0 + tx];
        }
        __syncthreads();
        #pragma unroll
        for (int i = 0; i < 4; i++) {
            int h = h0 + ty + i * 8;
            int l = l0 + tx;
            g_w1h[((size_t)k * H_DIM + h) * L_DIM + l] = __float2half_rn(sbuf[tx * 33 + ty + i * 8]);
        }
    }
}

// ---------------- 2) fused grouping + prefix + scatter + tile table (1 block) ----
#define GS_THREADS 1024
#define GS_PER 4   // 4096 / 1024
__global__ void __launch_bounds__(GS_THREADS) k_groupscan(const float* __restrict__ q,
                                                          const int* __restrict__ ch, int B) {
    __shared__ int cnt[K_EXP], fill[K_EXP], soff[K_EXP + 1];
    int tid = threadIdx.x;
    if (tid < K_EXP) { cnt[tid] = 0; fill[tid] = 0; }
    __syncthreads();
    int myg[GS_PER];
    #pragma unroll
    for (int j = 0; j < GS_PER; j++) {
        int b = tid + j * GS_THREADS;
        int c = ch[b];
        float v = q[b];
        int g = (v <= g_lq[c]) ? 2 : ((v >= g_uq[c]) ? 0 : 1);
        myg[j] = g;
        atomicAdd(&cnt[g], 1);
    }
    __syncthreads();
    if (tid == 0) {
        soff[0] = 0;
        for (int k = 0; k < K_EXP; k++) soff[k + 1] = soff[k] + cnt[k];
        for (int k = 0; k <= K_EXP; k++) g_off[k] = soff[k];
        int nt = 0;
        for (int k = 0; k < K_EXP; k++)
            for (int t0 = 0; t0 < cnt[k]; t0 += 128) {
                g_tile_g[nt] = k; g_tile_r0[nt] = t0; nt++;
            }
        g_ntiles = nt;
    }
    __syncthreads();
    #pragma unroll
    for (int j = 0; j < GS_PER; j++) {
        int b = tid + j * GS_THREADS;
        int g = myg[j];
        int p = atomicAdd(&fill[g], 1);
        g_idx[soff[g] + p] = b;
    }
}

// ---------------- 3) fp16 mma.sync GEMM: 128x128, occ-1, 3-deep B pipeline --------
// (R11 config verbatim — converged local optimum)
#define TSZ   (128 * AST * 2)     // 18432
#define SM_A  1024
#define SM_B  (SM_A + 2 * TSZ)
#define SMEM_GEMM (SM_B + 3 * TSZ)   // 93184

__global__ void __launch_bounds__(256, 1) k_gemm(const float* __restrict__ zf) {
    int tile = blockIdx.x;
    if (tile >= g_ntiles) return;
    int nh = blockIdx.y, split = blockIdx.z;
    extern __shared__ char smem[];
    uint32_t sb = smem_u32(smem);
    int tid = threadIdx.x, wid = tid >> 5, lane = tid & 31;
    int wm = wid >> 2, wn = wid & 3;   // 2 x 4 warp grid; warp tile 64m x 32n

    int g = g_tile_g[tile], r0 = g_tile_r0[tile];
    int off = g_off[g], cnt = g_off[g + 1] - off;
    if (tid < 128) ((int*)smem)[tid] = g_idx[off + min(r0 + tid, cnt - 1)];
    __syncthreads();

    // A gmem pointers (8 float4 per thread per K-tile)
    const float* arow[8];
    uint32_t a_st[8];
    #pragma unroll
    for (int i = 0; i < 8; i++) {
        int chunk = tid + 256 * i;
        int row = chunk >> 4, c4 = chunk & 15;
        arow[i] = zf + (size_t)(((const int*)smem)[row]) * L_DIM + split * KSEG + c4 * 4;
        a_st[i] = (uint32_t)(row * AST + c4 * 4) * 2;
    }
    // B gmem pointers (4 x 16B per thread per K-tile)
    const __half* bhp[4];
    uint32_t b_st[4];
    #pragma unroll
    for (int i = 0; i < 4; i++) {
        int chunk = tid + 256 * i;
        int r = chunk >> 3, c = chunk & 7;
        bhp[i] = g_w1h + ((size_t)g * H_DIM + nh * 128 + r) * L_DIM + split * KSEG + c * 8;
        b_st[i] = (uint32_t)(r * AST + c * 8) * 2;
    }
    // ldmatrix per-thread base offsets
    uint32_t a_ld = (uint32_t)((wm * 64 + (lane & 15)) * AST + (lane >> 4) * 8) * 2;
    uint32_t b_ld = (uint32_t)((wn * 32 + (lane & 7) + ((lane >> 4) << 3)) * AST
                               + ((lane >> 3) & 1) * 8) * 2;

    float acc[4][4][4];
    #pragma unroll
    for (int mi = 0; mi < 4; mi++)
        #pragma unroll
        for (int ni = 0; ni < 4; ni++)
            #pragma unroll
            for (int r = 0; r < 4; r++) acc[mi][ni][r] = 0.f;

    float4 areg[8];
    // prologue: commit B(0), B(1) as separate groups; A(0) -> STS buf0; A(1) -> regs
    #pragma unroll
    for (int i = 0; i < 4; i++) cp16(sb + SM_B + b_st[i], bhp[i]);
    CP_COMMIT();
    #pragma unroll
    for (int i = 0; i < 4; i++) cp16(sb + SM_B + TSZ + b_st[i], bhp[i] + KT);
    CP_COMMIT();
    #pragma unroll
    for (int i = 0; i < 8; i++) areg[i] = *(const float4*)(arow[i]);
    #pragma unroll
    for (int i = 0; i < 8; i++) {
        float4 v = areg[i];
        __half2 h01 = __floats2half2_rn(v.x, v.y);
        __half2 h23 = __floats2half2_rn(v.z, v.w);
        *(uint2*)(smem + SM_A + a_st[i]) = make_uint2(*(uint32_t*)&h01, *(uint32_t*)&h23);
    }
    #pragma unroll
    for (int i = 0; i < 8; i++) areg[i] = *(const float4*)(arow[i] + KT);

    for (int t = 0; t < NIT; t++) {
        uint32_t a_bo = (t & 1) ? TSZ : 0;
        uint32_t a_bn = (t & 1) ? 0 : TSZ;
        uint32_t b_bo = (uint32_t)(t % 3) * TSZ;
        bool more = (t + 1 < NIT);

        if (more) { CP_WAIT1(); } else { CP_WAIT0(); }
        __syncthreads();   // A(t) STS + B(t) visible; tile t-1 reads complete

        if (t + 2 < NIT) {
            int kn = (t + 2) * KT;
            uint32_t b_bn = (uint32_t)((t + 2) % 3) * TSZ;
            #pragma unroll
            for (int i = 0; i < 4; i++) cp16(sb + SM_B + b_bn + b_st[i], bhp[i] + kn);
            CP_COMMIT();
        }

        #pragma unroll
        for (int ks = 0; ks < 2; ks++) {
            uint32_t ah[4][4], bf[8];
            #pragma unroll
            for (int mi = 0; mi < 4; mi++)
                ldsm_x4(ah[mi], sb + SM_A + a_bo + a_ld + (uint32_t)(mi * 16 * AST) * 2 + ks * 32);
            ldsm_x4(bf + 0, sb + SM_B + b_bo + b_ld + ks * 32);
            ldsm_x4(bf + 4, sb + SM_B + b_bo + b_ld + (uint32_t)(16 * AST) * 2 + ks * 32);
            #pragma unroll
            for (int mi = 0; mi < 4; mi++)
                #pragma unroll
                for (int ni = 0; ni < 4; ni++)
                    mma_f16(acc[mi][ni], ah[mi], bf + ni * 2);
        }

        if (more) {
            #pragma unroll
            for (int i = 0; i < 8; i++) {
                float4 v = areg[i];
                __half2 h01 = __floats2half2_rn(v.x, v.y);
                __half2 h23 = __floats2half2_rn(v.z, v.w);
                *(uint2*)(smem + SM_A + a_bn + a_st[i]) =
                    make_uint2(*(uint32_t*)&h01, *(uint32_t*)&h23);
            }
            if (t + 2 < NIT) {
                int k2 = (t + 2) * KT;
                #pragma unroll
                for (int i = 0; i < 8; i++) areg[i] = *(const float4*)(arow[i] + k2);
            }
        }

        #pragma unroll
        for (int ks = 2; ks < 4; ks++) {
            uint32_t ah[4][4], bf[8];
            #pragma unroll
            for (int mi = 0; mi < 4; mi++)
                ldsm_x4(ah[mi], sb + SM_A + a_bo + a_ld + (uint32_t)(mi * 16 * AST) * 2 + ks * 32);
            ldsm_x4(bf + 0, sb + SM_B + b_bo + b_ld + ks * 32);
            ldsm_x4(bf + 4, sb + SM_B + b_bo + b_ld + (uint32_t)(16 * AST) * 2 + ks * 32);
            #pragma unroll
            for (int mi = 0; mi < 4; mi++)
                #pragma unroll
                for (int ni = 0; ni < 4; ni++)
                    mma_f16(acc[mi][ni], ah[mi], bf + ni * 2);
        }
    }

    // store fp32 partials
    float* pb = g_part + ((size_t)(split * TILE_MAX + tile) * 2 + nh) * (128 * 128);
    #pragma unroll
    for (int mi = 0; mi < 4; mi++)
        #pragma unroll
        for (int ni = 0; ni < 4; ni++) {
            int row = wm * 64 + mi * 16 + (lane >> 2);
            int col = wn * 32 + ni * 8 + (lane & 3) * 2;
            *(float2*)(pb + (size_t)row * 128 + col)       = make_float2(acc[mi][ni][0], acc[mi][ni][1]);
            *(float2*)(pb + (size_t)(row + 8) * 128 + col) = make_float2(acc[mi][ni][2], acc[mi][ni][3]);
        }
}

// ---------------- 4) reduce split-K + bias + exact gelu + head dot (vectorized) ---
// grid (TILE_MAX, 4): 140 CTAs; lane handles 8 consecutive cols via float4 pairs
__global__ void __launch_bounds__(256) k_epi(const float* __restrict__ b1) {
    int tile = blockIdx.x;
    if (tile >= g_ntiles) return;
    int g = g_tile_g[tile], r0 = g_tile_r0[tile];
    int off = g_off[g], cnt = g_off[g + 1] - off;
    int wid = threadIdx.x >> 5, lane = threadIdx.x & 31;
    int rbase = blockIdx.y * 32;
    float c2 = g_c2h[g];
    int c0 = lane * 8, nh2 = c0 >> 7, cc = c0 & 127;
    float4 bA = *(const float4*)(b1 + g * H_DIM + c0);
    float4 bB = *(const float4*)(b1 + g * H_DIM + c0 + 4);
    float4 wA = *(const float4*)(g_w2h + g * H_DIM + c0);
    float4 wB = *(const float4*)(g_w2h + g * H_DIM + c0 + 4);
    for (int rr = rbase + wid; rr < rbase + 32; rr += 8) {
        int r = r0 + rr;
        if (r >= cnt) continue;
        float4 xA = make_float4(0.f, 0.f, 0.f, 0.f), xB = xA;
        #pragma unroll
        for (int s = 0; s < NSPLIT; s++) {
            const float* p = g_part + (((size_t)(s * TILE_MAX + tile) * 2 + nh2) * 128 + rr) * 128 + cc;
            float4 v0 = *(const float4*)p;
            float4 v1 = *(const float4*)(p + 4);
            xA.x += v0.x; xA.y += v0.y; xA.z += v0.z; xA.w += v0.w;
            xB.x += v1.x; xB.y += v1.y; xB.z += v1.z; xB.w += v1.w;
        }
        float vs[8] = {xA.x + bA.x, xA.y + bA.y, xA.z + bA.z, xA.w + bA.w,
                       xB.x + bB.x, xB.y + bB.y, xB.z + bB.z, xB.w + bB.w};
        float ws[8] = {wA.x, wA.y, wA.z, wA.w, wB.x, wB.y, wB.z, wB.w};
        float acc = 0.f;
        #pragma unroll
        for (int i = 0; i < 8; i++) {
            float x = vs[i];
            float ge = 0.5f * x * (1.0f + erff(x * 0.7071067811865475f));
            acc += ge * ws[i];
        }
        #pragma unroll
        for (int o = 16; o; o >>= 1) acc += __shfl_xor_sync(0xffffffffu, acc, o);
        if (lane == 0) g_logits[g_idx[off + r]] = acc + c2;
    }
}

// ---------------- 5) per-channel softmax, scaled by q ----------------
__global__ void k_softmax(const float* __restrict__ q, const int* __restrict__ ch,
                          float* __restrict__ out, int B) {
    int c = blockIdx.x;
    __shared__ float red[256];
    int tid = threadIdx.x;
    float m = -INFINITY;
    for (int b = tid; b < B; b += 256) if (ch[b] == c) m = fmaxf(m, g_logits[b]);
    red[tid] = m; __syncthreads();
    for (int s = 128; s; s >>= 1) { if (tid < s) red[tid] = fmaxf(red[tid], red[tid + s]); __syncthreads(); }
    m = red[0]; __syncthreads();
    float sum = 0.f;
    for (int b = tid; b < B; b += 256) if (ch[b] == c) sum += expf(g_logits[b] - m);
    red[tid] = sum; __syncthreads();
    for (int s = 128; s; s >>= 1) { if (tid < s) red[tid] += red[tid + s]; __syncthreads(); }
    sum = red[0];
    for (int b = tid; b < B; b += 256)
        if (ch[b] == c) out[b] = q[b] * (expf(g_logits[b] - m) / sum);
}

// ---------------- launch ----------------
extern "C" void kernel_launch(void* const* d_in, const int* in_sizes, int n_in,
                              void* d_out, int out_size) {
    const float* z  = (const float*)d_in[0];
    const float* q  = (const float*)d_in[1];
    const int*   ch = (const int*)  d_in[2];
    const float* W1 = (const float*)d_in[3];
    const float* b1 = (const float*)d_in[4];
    const float* W2 = (const float*)d_in[5];
    const float* b2 = (const float*)d_in[6];
    const float* Wh = (const float*)d_in[7];
    const float* bh = (const float*)d_in[8];
    float* out = (float*)d_out;
    int B = in_sizes[1];

    static int smem_set = 0;
    if (!smem_set) {
        cudaFuncSetAttribute(k_gemm, cudaFuncAttributeMaxDynamicSharedMemorySize, SMEM_GEMM);
        smem_set = 1;
    }

    k_prep<<<PREP_BLKS, 256>>>(W1, W2, Wh, b2, bh, q, ch);
    k_groupscan<<<1, GS_THREADS>>>(q, ch, B);
    k_gemm<<<dim3(TILE_MAX, 2, NSPLIT), 256, SMEM_GEMM>>>(z);
    k_epi<<<dim3(TILE_MAX, 4), 256>>>(b1);
    k_softmax<<<C_CH, 256>>>(q, ch, out, B);
}